// round 5
// baseline (speedup 1.0000x reference)
#include <cuda_runtime.h>
#include <math.h>

#define F_IN   512
#define HID    16
#define CLS    40
#define N_MAX  100000
#define E_MAX  3400000

// ---------------- scratch (static device globals; no allocation) ------------
__device__ float  g_dis[N_MAX];            // deg -> dis = rsqrt(deg)
__device__ float  g_norm[E_MAX];           // per-edge norm
__device__ float4 g_h1[N_MAX * 4];         // h1 (then reused for relu'd r)
__device__ float4 g_agg1[N_MAX * 4];
__device__ float4 g_agg2[N_MAX * 4];

// vectorized fp32 reduction to global (sm_90+)
__device__ __forceinline__ void red_add_v4(float4* addr, float4 v) {
    asm volatile("red.global.add.v4.f32 [%0], {%1,%2,%3,%4};"
                 :: "l"(addr), "f"(v.x), "f"(v.y), "f"(v.z), "f"(v.w)
                 : "memory");
}

// ---------------- init: dis=1 (self-loop weight), aggs=0 --------------------
__global__ void init_kernel(int N) {
    int i = blockIdx.x * blockDim.x + threadIdx.x;
    if (i < N * 4) {
        float4 z = make_float4(0.f, 0.f, 0.f, 0.f);
        g_agg1[i] = z;
        g_agg2[i] = z;
    }
    if (i < N) g_dis[i] = 1.0f;
}

// deg[col] += w
__global__ void deg_kernel(const int* __restrict__ col, const float* __restrict__ w, int E) {
    int e = blockIdx.x * blockDim.x + threadIdx.x;
    if (e < E) atomicAdd(&g_dis[col[e]], w[e]);
}

// dis = rsqrt(deg)
__global__ void dis_kernel(int N) {
    int i = blockIdx.x * blockDim.x + threadIdx.x;
    if (i < N) g_dis[i] = rsqrtf(fmaxf(g_dis[i], 1e-12f));
}

// norm[e] = dis[row]*w*dis[col]
__global__ void norm_kernel(const int* __restrict__ ei, const float* __restrict__ w, int E) {
    int e = blockIdx.x * blockDim.x + threadIdx.x;
    if (e < E) g_norm[e] = g_dis[ei[e]] * w[e] * g_dis[ei[E + e]];
}

// ---------------- dense GEMM: h1 = x @ W1  (N x 512 @ 512 x 16) -------------
#define GT    128     // threads per block
#define GR    4       // rows per thread
#define GROWS (GT*GR) // 512 rows per block
#define KC    16      // k-chunk

__global__ __launch_bounds__(GT) void gemm1_kernel(const float* __restrict__ x,
                                                   const float* __restrict__ W1,
                                                   int N) {
    __shared__ float xs[GROWS][KC + 1];   // +1 pad: conflict-free column reads
    __shared__ float ws[KC][HID];
    int r0 = blockIdx.x * GROWS;

    float acc[GR][HID];
    #pragma unroll
    for (int a = 0; a < GR; a++)
        #pragma unroll
        for (int j = 0; j < HID; j++) acc[a][j] = 0.f;

    for (int kc = 0; kc < F_IN; kc += KC) {
        __syncthreads();
        for (int i = threadIdx.x; i < KC * HID; i += GT)
            ws[i / HID][i % HID] = W1[(kc + i / HID) * HID + (i % HID)];
        for (int idx = threadIdx.x; idx < GROWS * (KC / 4); idx += GT) {
            int rl  = idx / (KC / 4);
            int c4  = idx % (KC / 4);
            int row = r0 + rl;
            float4 v = make_float4(0.f, 0.f, 0.f, 0.f);
            if (row < N)
                v = *(const float4*)(x + (size_t)row * F_IN + kc + c4 * 4);
            xs[rl][c4 * 4 + 0] = v.x;
            xs[rl][c4 * 4 + 1] = v.y;
            xs[rl][c4 * 4 + 2] = v.z;
            xs[rl][c4 * 4 + 3] = v.w;
        }
        __syncthreads();

        #pragma unroll 4
        for (int kk = 0; kk < KC; kk++) {
            float wv[HID];
            #pragma unroll
            for (int j = 0; j < HID; j++) wv[j] = ws[kk][j];
            #pragma unroll
            for (int a = 0; a < GR; a++) {
                float xv = xs[threadIdx.x + a * GT][kk];
                #pragma unroll
                for (int j = 0; j < HID; j++)
                    acc[a][j] = fmaf(xv, wv[j], acc[a][j]);
            }
        }
    }

    #pragma unroll
    for (int a = 0; a < GR; a++) {
        int row = r0 + threadIdx.x + a * GT;
        if (row < N) {
            #pragma unroll
            for (int q = 0; q < 4; q++)
                g_h1[row * 4 + q] = make_float4(acc[a][4*q+0], acc[a][4*q+1],
                                                acc[a][4*q+2], acc[a][4*q+3]);
        }
    }
}

// ---------------- edge scatter: dst[col] += norm * src[row] (16 floats) -----
__global__ void scatter_kernel(const int* __restrict__ ei, int E, int pass) {
    int e = blockIdx.x * blockDim.x + threadIdx.x;
    if (e >= E) return;
    int r = ei[e];
    int c = ei[E + e];
    float nrm = g_norm[e];
    const float4* src = g_h1;
    float4* dst = (pass == 0) ? g_agg1 : g_agg2;
    #pragma unroll
    for (int q = 0; q < 4; q++) {
        float4 s = src[r * 4 + q];
        red_add_v4(dst + c * 4 + q,
                   make_float4(nrm * s.x, nrm * s.y, nrm * s.z, nrm * s.w));
    }
}

// ---------------- r = relu(agg1 + dis^2*h1 + b1)  (writes back into g_h1) ---
__global__ void relu_kernel(const float* __restrict__ b1, int N) {
    int idx = blockIdx.x * blockDim.x + threadIdx.x;
    if (idx >= N * 4) return;
    int i = idx >> 2;
    int q = idx & 3;
    float d  = g_dis[i];
    float d2 = d * d;
    float4 a = g_agg1[idx];
    float4 h = g_h1[idx];
    float4 r;
    r.x = fmaxf(fmaf(d2, h.x, a.x) + __ldg(b1 + q * 4 + 0), 0.f);
    r.y = fmaxf(fmaf(d2, h.y, a.y) + __ldg(b1 + q * 4 + 1), 0.f);
    r.z = fmaxf(fmaf(d2, h.z, a.z) + __ldg(b1 + q * 4 + 2), 0.f);
    r.w = fmaxf(fmaf(d2, h.w, a.w) + __ldg(b1 + q * 4 + 3), 0.f);
    g_h1[idx] = r;
}

// ---------------- epilogue: (agg2 + dis^2*r) @ W2 + b2 -> log_softmax -------
__global__ __launch_bounds__(128) void final_kernel(const float* __restrict__ W2,
                                                    const float* __restrict__ b2,
                                                    float* __restrict__ out,
                                                    int N) {
    __shared__ float w2s[HID][CLS];
    __shared__ float b2s[CLS];
    for (int i = threadIdx.x; i < HID * CLS; i += blockDim.x)
        w2s[i / CLS][i % CLS] = W2[i];
    if (threadIdx.x < CLS) b2s[threadIdx.x] = b2[threadIdx.x];
    __syncthreads();

    int i = blockIdx.x * blockDim.x + threadIdx.x;
    if (i >= N) return;

    float d  = g_dis[i];
    float d2 = d * d;
    float t[HID];
    #pragma unroll
    for (int q = 0; q < 4; q++) {
        float4 a = g_agg2[i * 4 + q];
        float4 r = g_h1[i * 4 + q];
        t[4*q+0] = fmaf(d2, r.x, a.x);
        t[4*q+1] = fmaf(d2, r.y, a.y);
        t[4*q+2] = fmaf(d2, r.z, a.z);
        t[4*q+3] = fmaf(d2, r.w, a.w);
    }

    float acc[CLS];
    #pragma unroll
    for (int j = 0; j < CLS; j++) acc[j] = b2s[j];
    #pragma unroll
    for (int k = 0; k < HID; k++) {
        float tv = t[k];
        #pragma unroll
        for (int j = 0; j < CLS; j++)
            acc[j] = fmaf(tv, w2s[k][j], acc[j]);
    }

    // log_softmax over CLS
    float m = acc[0];
    #pragma unroll
    for (int j = 1; j < CLS; j++) m = fmaxf(m, acc[j]);
    float s = 0.f;
    #pragma unroll
    for (int j = 0; j < CLS; j++) s += expf(acc[j] - m);
    float lse = m + logf(s);

    float* o = out + (size_t)i * CLS;
    #pragma unroll
    for (int q = 0; q < CLS / 4; q++) {
        float4 v = make_float4(acc[4*q+0] - lse, acc[4*q+1] - lse,
                               acc[4*q+2] - lse, acc[4*q+3] - lse);
        *(float4*)(o + 4 * q) = v;
    }
}

// ---------------------------------------------------------------------------
extern "C" void kernel_launch(void* const* d_in, const int* in_sizes, int n_in,
                              void* d_out, int out_size) {
    const float* x  = (const float*)d_in[0];
    const int*   ei = (const int*)d_in[1];
    const float* ew = (const float*)d_in[2];
    const float* W1 = (const float*)d_in[3];
    const float* b1 = (const float*)d_in[4];
    const float* W2 = (const float*)d_in[5];
    const float* b2 = (const float*)d_in[6];
    float* out = (float*)d_out;

    int N = in_sizes[0] / F_IN;     // 100000
    int E = in_sizes[2];            // 3200000

    const int T = 256;
    init_kernel<<<(N * 4 + T - 1) / T, T>>>(N);
    deg_kernel<<<(E + T - 1) / T, T>>>(ei + E, ew, E);
    dis_kernel<<<(N + T - 1) / T, T>>>(N);
    norm_kernel<<<(E + T - 1) / T, T>>>(ei, ew, E);
    gemm1_kernel<<<(N + GROWS - 1) / GROWS, GT>>>(x, W1, N);
    scatter_kernel<<<(E + T - 1) / T, T>>>(ei, E, 0);
    relu_kernel<<<(N * 4 + T - 1) / T, T>>>(b1, N);
    scatter_kernel<<<(E + T - 1) / T, T>>>(ei, E, 1);
    final_kernel<<<(N + 127) / 128, 128>>>(W2, b2, out, N);
}